// round 7
// baseline (speedup 1.0000x reference)
#include <cuda_runtime.h>
#include <math.h>

#define Xd 32
#define Yd 16
#define Nn 8192          // 32*16*16
#define Cc 4
#define NITER 5
#define ALPHA 5.0f
#define BETA  5.0f
#define GAMMA 5.0f
#define DEG 7
#define RK 36            // #(i,j), i+j<=7
#define NBLK (RK * Cc + Cc)   // 148 co-resident blocks

typedef unsigned long long ull;

// shared layout (float offsets)
#define O_A   0                 // 8192: std input field
#define O_B   8192              // 9216: conv-x out (std) / conv-z out (padded 18)
#define O_P   17408             // 9216: conv-y out (padded 18)
#define O_TBL 26624
#define SMEM_FLOATS (26624 + 352)
#define SMEM_BYTES (SMEM_FLOATS * 4)

// ---- static device scratch ----
__device__ float g_phi[RK][Nn];      // immutable after setup
__device__ float g_e[Nn];
__device__ float g_pre1[Nn];
__device__ float g_pre2[Nn];
__device__ float g_part[NBLK][Nn];
__device__ float g_q[2][Cc][Nn];
__device__ unsigned g_arr[NBLK];     // per-block arrival flags (monotonic)

__device__ __forceinline__ void ffma2(ull& d, ull a, ull b) {
    asm("fma.rn.f32x2 %0, %1, %2, %0;" : "+l"(d) : "l"(a), "l"(b));
}
__device__ __forceinline__ float lo2(ull v) { return __uint_as_float((unsigned)v); }
__device__ __forceinline__ float hi2(ull v) { return __uint_as_float((unsigned)(v >> 32)); }

// ---- symmetric grid barrier: every block polls the flag array directly ----
__device__ __forceinline__ void gbar(unsigned tgt, int b, int tid) {
    __syncthreads();
    if (tid == 0) { __threadfence(); *(volatile unsigned*)&g_arr[b] = tgt; }
    if (tid < NBLK) {
        while (*(volatile unsigned*)&g_arr[tid] < tgt) { }
    }
    __syncthreads();
}

// ---- separable 3D conv: in sm[O_A] (std) -> out sm[O_B] (padded 18) ----
__device__ __forceinline__ void conv3d(float* sm, const float* wx2, const float* wy2,
                                       const float* Dz, int tid) {
    float* sA = sm + O_A;
    float* sB = sm + O_B;
    float* sP = sm + O_P;
    __syncthreads();
    // conv-x: sA(std) -> sB(std). f32x2 lanes = yz pair; rolling dup weights.
    {
        int warp = tid >> 5, lane = tid & 31;
        int xg = (warp >> 2) << 2;
        int yz = ((warp & 3) << 6) + (lane << 1);
        ull a0 = 0, a1 = 0, a2 = 0, a3 = 0;
        ull w0 = *(const ull*)(wx2 + 2 * (xg + 0));
        ull w1 = *(const ull*)(wx2 + 2 * (xg + 1));
        ull w2 = *(const ull*)(wx2 + 2 * (xg + 2));
        ull w3 = *(const ull*)(wx2 + 2 * (xg + 3));
#pragma unroll
        for (int xp = 0; xp < Xd; xp++) {
            ull v = *(const ull*)(sA + (xp << 8) + yz);
            ffma2(a0, w0, v); ffma2(a1, w1, v);
            ffma2(a2, w2, v); ffma2(a3, w3, v);
            if (xp < Xd - 1) {
                w3 = w2; w2 = w1; w1 = w0;
                int d = xg - xp - 1; if (d < 0) d = -d;
                w0 = *(const ull*)(wx2 + 2 * d);
            }
        }
        *(ull*)(sB + ((xg + 0) << 8) + yz) = a0;
        *(ull*)(sB + ((xg + 1) << 8) + yz) = a1;
        *(ull*)(sB + ((xg + 2) << 8) + yz) = a2;
        *(ull*)(sB + ((xg + 3) << 8) + yz) = a3;
    }
    __syncthreads();
    // conv-y: sB(std) -> sP(padded 18)
    {
        int unit = tid >> 2, q = tid & 3;
        int x = unit >> 3, zp = unit & 7;
        int ibase = (x << 8) + (zp << 1);
        int yg = q << 2;
        ull a0 = 0, a1 = 0, a2 = 0, a3 = 0;
        ull w0 = *(const ull*)(wy2 + 2 * (yg + 0));
        ull w1 = *(const ull*)(wy2 + 2 * (yg + 1));
        ull w2 = *(const ull*)(wy2 + 2 * (yg + 2));
        ull w3 = *(const ull*)(wy2 + 2 * (yg + 3));
#pragma unroll
        for (int yp = 0; yp < Yd; yp++) {
            ull v = *(const ull*)(sB + ibase + (yp << 4));
            ffma2(a0, w0, v); ffma2(a1, w1, v);
            ffma2(a2, w2, v); ffma2(a3, w3, v);
            if (yp < Yd - 1) {
                w3 = w2; w2 = w1; w1 = w0;
                int d = yg - yp - 1; if (d < 0) d = -d;
                w0 = *(const ull*)(wy2 + 2 * d);
            }
        }
        int obase = (x << 4) * 18 + (zp << 1);
        *(ull*)(sP + obase + (yg + 0) * 18) = a0;
        *(ull*)(sP + obase + (yg + 1) * 18) = a1;
        *(ull*)(sP + obase + (yg + 2) * 18) = a2;
        *(ull*)(sP + obase + (yg + 3) * 18) = a3;
    }
    __syncthreads();
    // conv-z: sP(padded) -> sB(padded). 2 threads/line (warp-uniform half).
    {
        int line = tid & 511, half = tid >> 9;
        const float* in = sP + line * 18;
        float* outp = sB + line * 18;
        ull v[8];
#pragma unroll
        for (int p = 0; p < 8; p++) v[p] = *(const ull*)(in + 2 * p);
        if (half == 0) {
#pragma unroll
            for (int zo = 0; zo < 8; zo++) {
                ull acc = 0;
#pragma unroll
                for (int p = 0; p < 8; p++)
                    ffma2(acc, *(const ull*)(Dz + 2 * (zo - 2 * p + 14)), v[p]);
                outp[zo] = lo2(acc) + hi2(acc);
            }
        } else {
#pragma unroll
            for (int zo = 8; zo < 16; zo++) {
                ull acc = 0;
#pragma unroll
                for (int p = 0; p < 8; p++)
                    ffma2(acc, *(const ull*)(Dz + 2 * (zo - 2 * p + 14)), v[p]);
                outp[zo] = lo2(acc) + hi2(acc);
            }
        }
    }
    __syncthreads();
}

#define CONVOUT(sm, n) ((sm)[O_B + ((n) >> 4) * 18 + ((n) & 15)])

__global__ __launch_bounds__(1024, 1) void k_crf(
    const float* __restrict__ lu, const float* __restrict__ fp,
    const float* __restrict__ comp, float* __restrict__ out) {
    extern __shared__ float sm[];
    float* s_wax2 = sm + O_TBL;        // 64: bilateral x dup pairs
    float* s_wgx2 = s_wax2 + 64;       // 64: spatial x dup pairs
    float* s_way2 = s_wgx2 + 64;       // 32: bilateral y dup pairs
    float* s_wgy2 = s_way2 + 32;       // 32: spatial y dup pairs
    float* s_Da   = s_wgy2 + 32;       // bilateral z pair table
    float* s_Dg   = s_Da + 64;         // spatial z pair table
    float* s_cmp  = s_Dg + 64;         // 16
    __shared__ unsigned s_base;

    int tid = threadIdx.x;
    int b = blockIdx.x;

    if (tid == 0) s_base = *(volatile unsigned*)&g_arr[b];   // replay-safe base
    if (tid < 32) {
        float d2 = (float)tid * (float)tid;
        float wa = __expf(-0.5f * d2 / (ALPHA * ALPHA));
        float wg = __expf(-0.5f * d2 / (GAMMA * GAMMA));
        s_wax2[2 * tid] = wa; s_wax2[2 * tid + 1] = wa;
        s_wgx2[2 * tid] = wg; s_wgx2[2 * tid + 1] = wg;
        if (tid < 16) {
            s_way2[2 * tid] = wa; s_way2[2 * tid + 1] = wa;
            s_wgy2[2 * tid] = wg; s_wgy2[2 * tid + 1] = wg;
            s_cmp[tid] = comp[tid];
        }
    }
    if (tid < 30) {
        int j = tid - 14;
        int a0 = j < 0 ? -j : j;
        int a1 = j - 1 < 0 ? 1 - j : j - 1;
        s_Da[2 * tid]     = __expf(-0.5f * (float)(a0 * a0) / (ALPHA * ALPHA));
        s_Da[2 * tid + 1] = __expf(-0.5f * (float)(a1 * a1) / (ALPHA * ALPHA));
        s_Dg[2 * tid]     = __expf(-0.5f * (float)(a0 * a0) / (GAMMA * GAMMA));
        s_Dg[2 * tid + 1] = __expf(-0.5f * (float)(a1 * a1) / (GAMMA * GAMMA));
    }
    __syncthreads();
    unsigned base = s_base, bk = 0;

    // ==== phase A || B (concurrent) ====
    if (b < RK) {
        // B: rowsum conv for rank b, field computed from fp directly
        int i = 0, rr = b;
        while (rr > DEG - i) { rr -= DEG - i + 1; i++; }
        int j = rr;
        float fi = 1.f, fj = 1.f;
        for (int t = 2; t <= i; t++) fi *= (float)t;
        for (int t = 2; t <= j; t++) fj *= (float)t;
        float coef = rsqrtf(fi * fj);
        float ph[8];
#pragma unroll
        for (int u = 0; u < 8; u++) {
            int n = (u << 10) + tid;
            float fa = fp[n] * (1.0f / BETA);
            float fb = fp[Nn + n] * (1.0f / BETA);
            float e = __expf(-0.5f * (fa * fa + fb * fb));
            float pa = 1.f, pb = 1.f;
            for (int t = 0; t < i; t++) pa *= fa;
            for (int t = 0; t < j; t++) pb *= fb;
            ph[u] = coef * pa * pb;
            sm[O_A + n] = ph[u] * e;
        }
        conv3d(sm, s_wax2, s_way2, s_Da, tid);
#pragma unroll
        for (int u = 0; u < 8; u++) {
            int n = (u << 10) + tid;
            g_part[b][n] = ph[u] * CONVOUT(sm, n);
        }
    } else if (b < RK + 64) {
        // A: phi basis, e, q0  (64 blocks x 128 voxels)
        if (tid < 128) {
            int n = ((b - RK) << 7) + tid;
            float fa = fp[n] * (1.0f / BETA);
            float fb = fp[Nn + n] * (1.0f / BETA);
            float e = __expf(-0.5f * (fa * fa + fb * fb));
            g_e[n] = e;
            float fi = 1.f, pai = 1.f;
            int r = 0;
#pragma unroll
            for (int i = 0; i <= DEG; i++) {
                if (i > 0) fi *= (float)i;
                float fj = 1.f, pbj = 1.f;
#pragma unroll
                for (int j = 0; j <= DEG - i; j++) {
                    if (j > 0) fj *= (float)j;
                    g_phi[r][n] = rsqrtf(fi * fj) * pai * pbj;
                    pbj *= fb;
                    r++;
                }
                pai *= fa;
            }
            float l0 = lu[n], l1 = lu[Nn + n], l2 = lu[2 * Nn + n], l3 = lu[3 * Nn + n];
            float mx = fmaxf(fmaxf(l0, l1), fmaxf(l2, l3));
            float e0 = __expf(l0 - mx), e1 = __expf(l1 - mx);
            float e2 = __expf(l2 - mx), e3 = __expf(l3 - mx);
            float inv = 1.0f / (e0 + e1 + e2 + e3);
            g_q[0][0][n] = e0 * inv; g_q[0][1][n] = e1 * inv;
            g_q[0][2][n] = e2 * inv; g_q[0][3][n] = e3 * inv;
        }
    }
    gbar(base + (++bk), b, tid);

    // ==== phase C: normalization scales ====
    if (b < 32 && tid < 256) {
        int n = (b << 8) + tid;
        float s = 0.f;
#pragma unroll
        for (int r = 0; r < RK; r++) s += __ldcg(&g_part[r][n]);
        float e = g_e[n];
        g_pre1[n] = e * rsqrtf(e * s);
        int x = n >> 8, y = (n >> 4) & 15, z = n & 15;
        float Rx = 0.f, Ry = 0.f, Rz = 0.f;
#pragma unroll
        for (int d = 0; d < Xd; d++) Rx += s_wgx2[2 * ((x > d) ? (x - d) : (d - x))];
#pragma unroll
        for (int d = 0; d < Yd; d++) {
            Ry += s_wgy2[2 * ((y > d) ? (y - d) : (d - y))];
            Rz += s_wgy2[2 * ((z > d) ? (z - d) : (d - z))];
        }
        g_pre2[n] = rsqrtf(Rx * Ry * Rz);
    }
    gbar(base + (++bk), b, tid);

    // ==== phase E: 5 mean-field iterations ====
    int r = b >> 2, c = b & 3;
    bool sp = (r == RK);
    int r_eff = sp ? 0 : r;
    const float4* phi4 = (const float4*)g_phi[r_eff];   // immutable: L1 ok
    const float4* pre4 = sp ? (const float4*)g_pre2 : (const float4*)g_pre1;
    const float* wxE = sp ? s_wgx2 : s_wax2;
    const float* wyE = sp ? s_wgy2 : s_way2;
    const float* DzE = sp ? s_Dg : s_Da;
    for (int it = 0; it < NITER; it++) {
        {
            const float4* q4 = (const float4*)g_q[it & 1][c];
            float4* sa4 = (float4*)(sm + O_A);
#pragma unroll
            for (int u = 0; u < 2; u++) {
                int i4 = tid * 2 + u;
                float4 P = pre4[i4];
                float4 M;
                if (sp) M = P;
                else {
                    float4 A = phi4[i4];
                    M = make_float4(A.x * P.x, A.y * P.y, A.z * P.z, A.w * P.w);
                }
                float4 Q = __ldcg(q4 + i4);
                sa4[i4] = make_float4(M.x * Q.x, M.y * Q.y, M.z * Q.z, M.w * Q.w);
            }
            conv3d(sm, wxE, wyE, DzE, tid);
            float4* dst = (float4*)g_part[b];
#pragma unroll
            for (int u = 0; u < 2; u++) {
                int i4 = tid * 2 + u;
                float4 P = pre4[i4];
                float4 M;
                if (sp) M = P;
                else {
                    float4 A = phi4[i4];
                    M = make_float4(A.x * P.x, A.y * P.y, A.z * P.z, A.w * P.w);
                }
                int n0 = i4 << 2;
                dst[i4] = make_float4(M.x * CONVOUT(sm, n0),
                                      M.y * CONVOUT(sm, n0 + 1),
                                      M.z * CONVOUT(sm, n0 + 2),
                                      M.w * CONVOUT(sm, n0 + 3));
            }
        }
        gbar(base + (++bk), b, tid);
        // update: 128 blocks x 256 threads, one (n,c) per thread
        if (b < 128 && tid < 256) {
            int idx = (b << 8) + tid;
            int cc = idx & 3, n = idx >> 2;
            float u = 0.f;
#pragma unroll
            for (int k = 0; k <= RK; k++)
                u += __ldcg(&g_part[k * 4 + cc][n]);
            float v1 = __shfl_xor_sync(0xFFFFFFFFu, u, 1);
            float v2 = __shfl_xor_sync(0xFFFFFFFFu, u, 2);
            float v3 = __shfl_xor_sync(0xFFFFFFFFu, u, 3);
            float qu = s_cmp[cc * 4 + cc] * u
                     + s_cmp[cc * 4 + (cc ^ 1)] * v1
                     + s_cmp[cc * 4 + (cc ^ 2)] * v2
                     + s_cmp[cc * 4 + (cc ^ 3)] * v3;
            float lg = lu[cc * Nn + n] - qu;
            float m1 = fmaxf(lg, __shfl_xor_sync(0xFFFFFFFFu, lg, 1));
            float mx = fmaxf(m1, __shfl_xor_sync(0xFFFFFFFFu, m1, 2));
            float e = __expf(lg - mx);
            float s1 = e + __shfl_xor_sync(0xFFFFFFFFu, e, 1);
            float ss = s1 + __shfl_xor_sync(0xFFFFFFFFu, s1, 2);
            float qv = e / ss;
            if (it == NITER - 1) out[cc * Nn + n] = qv;
            else                 g_q[(it + 1) & 1][cc][n] = qv;
        }
        if (it < NITER - 1) gbar(base + (++bk), b, tid);
    }
}

extern "C" void kernel_launch(void* const* d_in, const int* in_sizes, int n_in,
                              void* d_out, int out_size) {
    const float* lu   = (const float*)d_in[0];
    const float* fp   = (const float*)d_in[1];
    const float* comp = (const float*)d_in[2];
    float* out = (float*)d_out;

    cudaFuncSetAttribute(k_crf, cudaFuncAttributeMaxDynamicSharedMemorySize, SMEM_BYTES);
    k_crf<<<NBLK, 1024, SMEM_BYTES>>>(lu, fp, comp, out);
}

// round 8
// speedup vs baseline: 1.3987x; 1.3987x over previous
#include <cuda_runtime.h>
#include <math.h>

#define Xd 32
#define Yd 16
#define Nn 8192          // 32*16*16
#define Cc 4
#define NITER 5
#define ALPHA 5.0f
#define BETA  5.0f
#define GAMMA 5.0f
#define DEG 7
#define RK 36            // #(i,j), i+j<=7
#define NBLK (RK * Cc + Cc)   // 148 co-resident blocks
#define SMEM_FLOATS (2 * Nn + 160)
#define SMEM_BYTES (SMEM_FLOATS * 4)

// ---- static device scratch (no allocations anywhere) ----
__device__ float g_phi[RK][Nn];      // phi, scaled in place to psi = phi*pre1
__device__ float g_e[Nn];
__device__ float g_pre1[Nn];
__device__ float g_pre2[Nn];
__device__ float g_part[NBLK][Nn];
__device__ float g_q[2][Cc][Nn];
__device__ unsigned g_arr[NBLK];     // per-block arrival flags (monotonic)
__device__ unsigned g_gen;           // published generation (monotonic)

// ---- observer grid barrier (R4-proven): block 0 watches flags, publishes gen ----
__device__ __forceinline__ void gbar(unsigned tgt, int b, int tid) {
    __syncthreads();
    if (b == 0) {
        if (tid == 0) { __threadfence(); *(volatile unsigned*)&g_arr[0] = tgt; }
        if (tid < NBLK) { while (*(volatile unsigned*)&g_arr[tid] < tgt) { } }
        __syncthreads();
        if (tid == 0) { __threadfence(); *(volatile unsigned*)&g_gen = tgt; }
    } else {
        if (tid == 0) {
            __threadfence();
            *(volatile unsigned*)&g_arr[b] = tgt;
            while (*(volatile unsigned*)&g_gen < tgt) { }
            __threadfence();
        }
        __syncthreads();
    }
}

// ---- separable 3D Gaussian conv over 32x16x16 field in shared memory ----
// input sa, result sb (sa clobbered). All branches warp-uniform.
__device__ __forceinline__ void conv3d(float* sa, float* sb,
                                       const float* wx, const float* wyz, int tid) {
    __syncthreads();
    // conv-x: sa -> sb (32 taps, stride 256). 8 outputs/thread, scalar columns,
    // rolling 8-weight window. Reads halved vs 4-output version.
    {
        int xg = (tid >> 8) << 3;        // x-group of 8 outputs
        int yz = tid & 255;
        float acc[8] = {0.f,0.f,0.f,0.f,0.f,0.f,0.f,0.f};
        float w[8];
#pragma unroll
        for (int k = 0; k < 8; k++) w[k] = wx[xg + k];   // xp=0: |xg+k|
#pragma unroll
        for (int xp = 0; xp < Xd; xp++) {
            float v = sa[(xp << 8) + yz];
#pragma unroll
            for (int k = 0; k < 8; k++) acc[k] += w[k] * v;
            if (xp < Xd - 1) {
#pragma unroll
                for (int k = 7; k >= 1; k--) w[k] = w[k - 1];
                int d = xg - xp - 1; if (d < 0) d = -d;
                w[0] = wx[d];
            }
        }
#pragma unroll
        for (int k = 0; k < 8; k++) sb[((xg + k) << 8) + yz] = acc[k];
    }
    __syncthreads();
    // conv-y: sb -> sa (16 taps, stride 16). 2 threads/line, half = tid>>9.
    {
        int line = tid & 511, half = tid >> 9;
        int z = line & 15, x = line >> 4;
        int base = (x << 8) + z;
        float lin[16], wv[16];
#pragma unroll
        for (int y = 0; y < Yd; y++) lin[y] = sb[base + (y << 4)];
#pragma unroll
        for (int d = 0; d < Yd; d++) wv[d] = wyz[d];
        if (half == 0) {
#pragma unroll
            for (int yo = 0; yo < 8; yo++) {
                float s = 0.f;
#pragma unroll
                for (int yp = 0; yp < Yd; yp++)
                    s += wv[(yo > yp) ? (yo - yp) : (yp - yo)] * lin[yp];
                sa[base + (yo << 4)] = s;
            }
        } else {
#pragma unroll
            for (int yo = 8; yo < 16; yo++) {
                float s = 0.f;
#pragma unroll
                for (int yp = 0; yp < Yd; yp++)
                    s += wv[(yo > yp) ? (yo - yp) : (yp - yo)] * lin[yp];
                sa[base + (yo << 4)] = s;
            }
        }
    }
    __syncthreads();
    // conv-z: sa -> sb (16 taps, stride 1). 2 threads/line, float4 I/O.
    {
        int line = tid & 511, half = tid >> 9;
        float l[16], wv[16];
        const float4* L4 = (const float4*)(sa + line * 16);
#pragma unroll
        for (int i = 0; i < 4; i++) {
            float4 v = L4[i];
            l[4*i] = v.x; l[4*i+1] = v.y; l[4*i+2] = v.z; l[4*i+3] = v.w;
        }
#pragma unroll
        for (int d = 0; d < Yd; d++) wv[d] = wyz[d];
        float o[8];
        if (half == 0) {
#pragma unroll
            for (int zo = 0; zo < 8; zo++) {
                float s = 0.f;
#pragma unroll
                for (int zp = 0; zp < 16; zp++)
                    s += wv[(zo > zp) ? (zo - zp) : (zp - zo)] * l[zp];
                o[zo] = s;
            }
        } else {
#pragma unroll
            for (int zo = 8; zo < 16; zo++) {
                float s = 0.f;
#pragma unroll
                for (int zp = 0; zp < 16; zp++)
                    s += wv[(zo > zp) ? (zo - zp) : (zp - zo)] * l[zp];
                o[zo - 8] = s;
            }
        }
        float4* O4 = (float4*)(sb + line * 16 + half * 8);
        O4[0] = make_float4(o[0], o[1], o[2], o[3]);
        O4[1] = make_float4(o[4], o[5], o[6], o[7]);
    }
    __syncthreads();
}

__global__ __launch_bounds__(1024, 1) void k_crf(
    const float* __restrict__ lu, const float* __restrict__ fp,
    const float* __restrict__ comp, float* __restrict__ out) {
    extern __shared__ float sm[];
    float* s_a   = sm;
    float* s_b   = sm + Nn;
    float* s_wax = sm + 2 * Nn;        // 32
    float* s_way = s_wax + 32;         // 16
    float* s_wgx = s_way + 16;         // 32
    float* s_wgy = s_wgx + 32;         // 16
    float* s_cmp = s_wgy + 16;         // 16
    __shared__ unsigned s_base;

    int tid = threadIdx.x;
    int b = blockIdx.x;

    if (tid == 0) s_base = *(volatile unsigned*)&g_arr[b];  // replay-safe base
    if (tid < 32) {
        float d2 = (float)tid * (float)tid;
        s_wax[tid] = __expf(-0.5f * d2 / (ALPHA * ALPHA));
        s_wgx[tid] = __expf(-0.5f * d2 / (GAMMA * GAMMA));
    }
    if (tid < 16) {
        float d2 = (float)tid * (float)tid;
        s_way[tid] = __expf(-0.5f * d2 / (ALPHA * ALPHA));
        s_wgy[tid] = __expf(-0.5f * d2 / (GAMMA * GAMMA));
        s_cmp[tid] = comp[tid];
    }
    __syncthreads();
    unsigned base = s_base, bk = 0;

    // ==== phase A || B (concurrent) ====
    if (b < RK) {
        // B: bilateral rowsum conv for rank b; phi recomputed locally from fp
        int i = 0, rr = b;
        while (rr > DEG - i) { rr -= DEG - i + 1; i++; }
        int j = rr;
        float fi = 1.f, fj = 1.f;
        for (int t = 2; t <= i; t++) fi *= (float)t;
        for (int t = 2; t <= j; t++) fj *= (float)t;
        float coef = rsqrtf(fi * fj);
        float ph[8];
#pragma unroll
        for (int u = 0; u < 8; u++) {
            int n = (u << 10) + tid;
            float fa = fp[n] * (1.0f / BETA);
            float fb = fp[Nn + n] * (1.0f / BETA);
            float e = __expf(-0.5f * (fa * fa + fb * fb));
            float pa = 1.f, pb = 1.f;
            for (int t = 0; t < i; t++) pa *= fa;
            for (int t = 0; t < j; t++) pb *= fb;
            ph[u] = coef * pa * pb;
            s_a[n] = ph[u] * e;
        }
        conv3d(s_a, s_b, s_wax, s_way, tid);
#pragma unroll
        for (int u = 0; u < 8; u++) {
            int n = (u << 10) + tid;
            g_part[b][n] = ph[u] * s_b[n];
        }
    } else if (b < RK + 64) {
        // A: phi basis, e, q0 (64 blocks x 128 voxels)
        if (tid < 128) {
            int n = ((b - RK) << 7) + tid;
            float fa = fp[n] * (1.0f / BETA);
            float fb = fp[Nn + n] * (1.0f / BETA);
            float e = __expf(-0.5f * (fa * fa + fb * fb));
            g_e[n] = e;
            float fi = 1.f, pai = 1.f;
            int r = 0;
#pragma unroll
            for (int i = 0; i <= DEG; i++) {
                if (i > 0) fi *= (float)i;
                float fj = 1.f, pbj = 1.f;
#pragma unroll
                for (int j = 0; j <= DEG - i; j++) {
                    if (j > 0) fj *= (float)j;
                    g_phi[r][n] = rsqrtf(fi * fj) * pai * pbj;
                    pbj *= fb;
                    r++;
                }
                pai *= fa;
            }
            float l0 = lu[n], l1 = lu[Nn + n], l2 = lu[2 * Nn + n], l3 = lu[3 * Nn + n];
            float mx = fmaxf(fmaxf(l0, l1), fmaxf(l2, l3));
            float e0 = __expf(l0 - mx), e1 = __expf(l1 - mx);
            float e2 = __expf(l2 - mx), e3 = __expf(l3 - mx);
            float inv = 1.0f / (e0 + e1 + e2 + e3);
            g_q[0][0][n] = e0 * inv; g_q[0][1][n] = e1 * inv;
            g_q[0][2][n] = e2 * inv; g_q[0][3][n] = e3 * inv;
        }
    }
    gbar(base + (++bk), b, tid);

    // ==== phase C: normalization scales (32 blocks x 256 threads) ====
    if (b < 32 && tid < 256) {
        int n = (b << 8) + tid;
        float s = 0.f;
#pragma unroll
        for (int r = 0; r < RK; r++) s += __ldcg(&g_part[r][n]);
        float e = g_e[n];
        g_pre1[n] = e * rsqrtf(e * s);
        int x = n >> 8, y = (n >> 4) & 15, z = n & 15;
        float Rx = 0.f, Ry = 0.f, Rz = 0.f;
#pragma unroll
        for (int d = 0; d < Xd; d++) Rx += s_wgx[(x > d) ? (x - d) : (d - x)];
#pragma unroll
        for (int d = 0; d < Yd; d++) {
            Ry += s_wgy[(y > d) ? (y - d) : (d - y)];
            Rz += s_wgy[(z > d) ? (z - d) : (d - z)];
        }
        g_pre2[n] = rsqrtf(Rx * Ry * Rz);
    }
    gbar(base + (++bk), b, tid);

    // ==== phase D: psi = phi * pre1 in place ====
    if (b < RK) {
#pragma unroll
        for (int u = 0; u < 8; u++) {
            int n = (u << 10) + tid;
            g_phi[b][n] *= g_pre1[n];
        }
    }
    gbar(base + (++bk), b, tid);

    // ==== phase E: 5 mean-field iterations ====
    int r = b >> 2, c = b & 3;
    bool sp = (r == RK);
    const float4* mul4 = sp ? (const float4*)g_pre2 : (const float4*)g_phi[r];
    const float* wxE = sp ? s_wgx : s_wax;
    const float* wyE = sp ? s_wgy : s_way;
    // hoisted update-phase constants (inputs immutable)
    int up_cc = 0, up_n = 0;
    float lun = 0.f;
    if (b < 128 && tid < 256) {
        int idx = (b << 8) + tid;
        up_cc = idx & 3; up_n = idx >> 2;
        lun = lu[up_cc * Nn + up_n];
    }
    for (int it = 0; it < NITER; it++) {
        {
            const float4* q4 = (const float4*)g_q[it & 1][c];
            float4* sa4 = (float4*)s_a;
#pragma unroll
            for (int u = 0; u < 2; u++) {
                int i4 = tid * 2 + u;
                float4 M = mul4[i4];          // immutable after phase D
                float4 Q = __ldcg(q4 + i4);   // mutable: L2-coherent
                sa4[i4] = make_float4(M.x * Q.x, M.y * Q.y, M.z * Q.z, M.w * Q.w);
            }
            conv3d(s_a, s_b, wxE, wyE, tid);
            const float4* sb4 = (const float4*)s_b;
            float4* dst = (float4*)g_part[b];
#pragma unroll
            for (int u = 0; u < 2; u++) {
                int i4 = tid * 2 + u;
                float4 M = mul4[i4];
                float4 V = sb4[i4];
                dst[i4] = make_float4(M.x * V.x, M.y * V.y, M.z * V.z, M.w * V.w);
            }
        }
        gbar(base + (++bk), b, tid);
        // update: 128 blocks x 256 threads, one (n,c) per thread
        if (b < 128 && tid < 256) {
            float u = 0.f;
#pragma unroll
            for (int k = 0; k <= RK; k++)
                u += __ldcg(&g_part[k * 4 + up_cc][up_n]);
            float v1 = __shfl_xor_sync(0xFFFFFFFFu, u, 1);
            float v2 = __shfl_xor_sync(0xFFFFFFFFu, u, 2);
            float v3 = __shfl_xor_sync(0xFFFFFFFFu, u, 3);
            float qu = s_cmp[up_cc * 4 + up_cc] * u
                     + s_cmp[up_cc * 4 + (up_cc ^ 1)] * v1
                     + s_cmp[up_cc * 4 + (up_cc ^ 2)] * v2
                     + s_cmp[up_cc * 4 + (up_cc ^ 3)] * v3;
            float lg = lun - qu;
            float m1 = fmaxf(lg, __shfl_xor_sync(0xFFFFFFFFu, lg, 1));
            float mx = fmaxf(m1, __shfl_xor_sync(0xFFFFFFFFu, m1, 2));
            float e = __expf(lg - mx);
            float s1 = e + __shfl_xor_sync(0xFFFFFFFFu, e, 1);
            float ss = s1 + __shfl_xor_sync(0xFFFFFFFFu, s1, 2);
            float qv = e / ss;
            if (it == NITER - 1) out[up_cc * Nn + up_n] = qv;
            else                 g_q[(it + 1) & 1][up_cc][up_n] = qv;
        }
        if (it < NITER - 1) gbar(base + (++bk), b, tid);
    }
}

extern "C" void kernel_launch(void* const* d_in, const int* in_sizes, int n_in,
                              void* d_out, int out_size) {
    const float* lu   = (const float*)d_in[0];
    const float* fp   = (const float*)d_in[1];
    const float* comp = (const float*)d_in[2];
    float* out = (float*)d_out;

    cudaFuncSetAttribute(k_crf, cudaFuncAttributeMaxDynamicSharedMemorySize, SMEM_BYTES);
    k_crf<<<NBLK, 1024, SMEM_BYTES>>>(lu, fp, comp, out);
}